// round 1
// baseline (speedup 1.0000x reference)
#include <cuda_runtime.h>
#include <math.h>

#define BB   8
#define SS   1024
#define DD   1024
#define HH   16
#define DK   64
#define DF   4096
#define NT   (BB*SS)        // 8192 tokens

// ---------------- scratch (static device globals; no allocation) ------------
__device__ float g_xq[NT*DD];          // LN output (reused for both LNs)
__device__ float g_q [NT*DD];
__device__ float g_k [NT*DD];
__device__ float g_v [NT*DD];
__device__ float g_ctx[NT*DD];
__device__ float g_x1[NT*DD];          // after bn1
__device__ float g_h [NT*DF];          // FFN hidden

// ---------------- generic tiled GEMM: C = A (MxK) * op(B) + epilogue --------
// BT=true : B is [N,K] row-major (computes A*B^T)   -> all Linear layers, scores
// BT=false: B is [K,N] row-major (computes A*B)     -> attn @ V
// Batched over blockIdx.z with offsets (z/16)*s1 + (z%16)*s2 per operand.
// MODE: 0 = +bias
//       1 = +bias +res, then per-channel BN
//       2 = +bias, exact GELU, then per-channel BN
//       3 = masked scale (scores): mask==0 ? -1e9 : acc*0.125
//       4 = raw
template<int BM,int BN,int BK,int TM,int TN,bool BT,int MODE>
__global__ void __launch_bounds__(256)
gemm_k(const float* __restrict__ A, int lda, long aS1, long aS2,
       const float* __restrict__ B, int ldb, long bS1, long bS2,
       float*       __restrict__ C, int ldc, long cS1, long cS2,
       int K,
       const float* __restrict__ bias,
       const float* __restrict__ res,
       const float* __restrict__ bng, const float* __restrict__ bnb,
       const float* __restrict__ bnm, const float* __restrict__ bnv,
       const int*   __restrict__ mask, int maskS1)
{
    const int z  = blockIdx.z;
    const int zb = z >> 4;     // z / 16
    const int zh = z & 15;     // z % 16
    A += (long)zb * aS1 + (long)zh * aS2;
    B += (long)zb * bS1 + (long)zh * bS2;
    C += (long)zb * cS1 + (long)zh * cS2;

    __shared__ float As[BK][BM];
    __shared__ float Bs[BK][BN];

    const int tid = threadIdx.x;
    const int m0  = blockIdx.y * BM;
    const int n0  = blockIdx.x * BN;
    constexpr int NTX = BN / TN;
    const int tx = tid % NTX;
    const int ty = tid / NTX;

    float acc[TM][TN];
    #pragma unroll
    for (int i = 0; i < TM; i++)
        #pragma unroll
        for (int j = 0; j < TN; j++) acc[i][j] = 0.0f;

    for (int k0 = 0; k0 < K; k0 += BK) {
        // ---- load A tile (BM x BK), float4 along K, transpose into smem ----
        {
            constexpr int KV  = BK / 4;
            constexpr int RPI = 256 / KV;
            #pragma unroll
            for (int r = 0; r < BM; r += RPI) {
                int m  = r + tid / KV;
                int kk = (tid % KV) * 4;
                float4 t = *(const float4*)(A + (long)(m0 + m) * lda + k0 + kk);
                As[kk+0][m] = t.x; As[kk+1][m] = t.y;
                As[kk+2][m] = t.z; As[kk+3][m] = t.w;
            }
        }
        // ---- load B tile ----
        if constexpr (BT) {
            constexpr int KV  = BK / 4;
            constexpr int RPI = 256 / KV;
            #pragma unroll
            for (int r = 0; r < BN; r += RPI) {
                int n  = r + tid / KV;
                int kk = (tid % KV) * 4;
                float4 t = *(const float4*)(B + (long)(n0 + n) * ldb + k0 + kk);
                Bs[kk+0][n] = t.x; Bs[kk+1][n] = t.y;
                Bs[kk+2][n] = t.z; Bs[kk+3][n] = t.w;
            }
        } else {
            constexpr int NV  = BN / 4;
            constexpr int RPI = 256 / NV;
            #pragma unroll
            for (int r = 0; r < BK; r += RPI) {
                int kk = r + tid / NV;
                int n  = (tid % NV) * 4;
                *(float4*)(&Bs[kk][n]) =
                    *(const float4*)(B + (long)(k0 + kk) * ldb + n0 + n);
            }
        }
        __syncthreads();

        // ---- compute ----
        #pragma unroll
        for (int kk = 0; kk < BK; kk++) {
            float a[TM], b[TN];
            #pragma unroll
            for (int i = 0; i < TM; i++) a[i] = As[kk][ty * TM + i];
            #pragma unroll
            for (int j = 0; j < TN; j++) b[j] = Bs[kk][tx * TN + j];
            #pragma unroll
            for (int i = 0; i < TM; i++)
                #pragma unroll
                for (int j = 0; j < TN; j++)
                    acc[i][j] = fmaf(a[i], b[j], acc[i][j]);
        }
        __syncthreads();
    }

    // ---- epilogue + store ----
    #pragma unroll
    for (int i = 0; i < TM; i++) {
        const int m = m0 + ty * TM + i;
        #pragma unroll
        for (int j = 0; j < TN; j++) {
            const int n = n0 + tx * TN + j;
            float t = acc[i][j];
            if constexpr (MODE == 0) {
                t += bias[n];
            } else if constexpr (MODE == 1) {
                t += bias[n] + res[(long)m * ldc + n];
                t = (t - bnm[n]) * rsqrtf(bnv[n] + 1e-5f) * bng[n] + bnb[n];
            } else if constexpr (MODE == 2) {
                t += bias[n];
                t = 0.5f * t * (1.0f + erff(t * 0.70710678118654752f));
                t = (t - bnm[n]) * rsqrtf(bnv[n] + 1e-5f) * bng[n] + bnb[n];
            } else if constexpr (MODE == 3) {
                t = (mask[(long)zb * maskS1 + n] == 0) ? -1e9f : t * 0.125f;
            }
            C[(long)m * ldc + n] = t;
        }
    }
}

// ---------------- LayerNorm over last dim (D=1024), 1 block/row -------------
__global__ void __launch_bounds__(256)
ln_k(const float* __restrict__ x, const float* __restrict__ g,
     const float* __restrict__ b, float* __restrict__ o)
{
    __shared__ float red[8];
    const long row = blockIdx.x;
    const int  t   = threadIdx.x;
    const int  lane = t & 31, w = t >> 5;

    float4 v = ((const float4*)(x + row * DD))[t];
    float s = v.x + v.y + v.z + v.w;
    #pragma unroll
    for (int off = 16; off; off >>= 1) s += __shfl_down_sync(0xffffffffu, s, off);
    if (!lane) red[w] = s;
    __syncthreads();
    if (t == 0) { float a = 0.f; for (int i = 0; i < 8; i++) a += red[i]; red[0] = a; }
    __syncthreads();
    const float mu = red[0] * (1.0f / DD);
    __syncthreads();

    float d0 = v.x - mu, d1 = v.y - mu, d2 = v.z - mu, d3 = v.w - mu;
    float sq = d0*d0 + d1*d1 + d2*d2 + d3*d3;
    #pragma unroll
    for (int off = 16; off; off >>= 1) sq += __shfl_down_sync(0xffffffffu, sq, off);
    if (!lane) red[w] = sq;
    __syncthreads();
    if (t == 0) { float a = 0.f; for (int i = 0; i < 8; i++) a += red[i]; red[0] = a; }
    __syncthreads();
    const float rs = rsqrtf(red[0] * (1.0f / DD) + 1e-5f);

    float4 g4 = ((const float4*)g)[t];
    float4 b4 = ((const float4*)b)[t];
    float4 r;
    r.x = d0 * rs * g4.x + b4.x;
    r.y = d1 * rs * g4.y + b4.y;
    r.z = d2 * rs * g4.z + b4.z;
    r.w = d3 * rs * g4.w + b4.w;
    ((float4*)(o + row * DD))[t] = r;
}

// ---------------- row softmax over S=1024, 1 block/row, in-place ------------
__global__ void __launch_bounds__(256)
softmax_k(float* __restrict__ a)
{
    __shared__ float red[8];
    const long row = blockIdx.x;
    const int  t   = threadIdx.x;
    const int  lane = t & 31, w = t >> 5;

    float4* p = (float4*)(a + row * (long)SS);
    float4 v = p[t];
    float mx = fmaxf(fmaxf(v.x, v.y), fmaxf(v.z, v.w));
    #pragma unroll
    for (int off = 16; off; off >>= 1)
        mx = fmaxf(mx, __shfl_down_sync(0xffffffffu, mx, off));
    if (!lane) red[w] = mx;
    __syncthreads();
    if (t == 0) { float m = red[0]; for (int i = 1; i < 8; i++) m = fmaxf(m, red[i]); red[0] = m; }
    __syncthreads();
    const float rmax = red[0];
    __syncthreads();

    float e0 = __expf(v.x - rmax), e1 = __expf(v.y - rmax);
    float e2 = __expf(v.z - rmax), e3 = __expf(v.w - rmax);
    float s = e0 + e1 + e2 + e3;
    #pragma unroll
    for (int off = 16; off; off >>= 1) s += __shfl_down_sync(0xffffffffu, s, off);
    if (!lane) red[w] = s;
    __syncthreads();
    if (t == 0) { float a2 = 0.f; for (int i = 0; i < 8; i++) a2 += red[i]; red[0] = a2; }
    __syncthreads();
    const float inv = 1.0f / red[0];

    p[t] = make_float4(e0 * inv, e1 * inv, e2 * inv, e3 * inv);
}

// ---------------- host orchestration ----------------------------------------
extern "C" void kernel_launch(void* const* d_in, const int* in_sizes, int n_in,
                              void* d_out, int out_size)
{
    const float* x    = (const float*)d_in[0];
    const int*   mask = (const int*)  d_in[1];
    const float* Wq = (const float*)d_in[2];  const float* bq = (const float*)d_in[3];
    const float* Wk = (const float*)d_in[4];  const float* bk = (const float*)d_in[5];
    const float* Wv = (const float*)d_in[6];  const float* bv = (const float*)d_in[7];
    const float* Wo = (const float*)d_in[8];  const float* bo = (const float*)d_in[9];
    const float* lag = (const float*)d_in[10]; const float* lab = (const float*)d_in[11];
    const float* W1 = (const float*)d_in[12]; const float* b1 = (const float*)d_in[13];
    const float* W2 = (const float*)d_in[14]; const float* b2 = (const float*)d_in[15];
    const float* lfg = (const float*)d_in[16]; const float* lfb = (const float*)d_in[17];
    const float* bnffg = (const float*)d_in[18]; const float* bnffb = (const float*)d_in[19];
    const float* bnffm = (const float*)d_in[20]; const float* bnffv = (const float*)d_in[21];
    const float* bn1g = (const float*)d_in[22]; const float* bn1b = (const float*)d_in[23];
    const float* bn1m = (const float*)d_in[24]; const float* bn1v = (const float*)d_in[25];
    const float* bn2g = (const float*)d_in[26]; const float* bn2b = (const float*)d_in[27];
    const float* bn2m = (const float*)d_in[28]; const float* bn2v = (const float*)d_in[29];

    float *xq, *q, *k, *v, *ctx, *x1, *h;
    cudaGetSymbolAddress((void**)&xq,  g_xq);
    cudaGetSymbolAddress((void**)&q,   g_q);
    cudaGetSymbolAddress((void**)&k,   g_k);
    cudaGetSymbolAddress((void**)&v,   g_v);
    cudaGetSymbolAddress((void**)&ctx, g_ctx);
    cudaGetSymbolAddress((void**)&x1,  g_x1);
    cudaGetSymbolAddress((void**)&h,   g_h);

    float* outx = (float*)d_out;                    // [B,S,D]
    float* outa = outx + (long)NT * DD;             // [B,H,S,S]

    // 1) pre-LN for query path
    ln_k<<<NT, 256>>>(x, lag, lab, xq);

    // 2) Q,K,V projections (NT GEMMs, M=8192 N=1024 K=1024)
    dim3 gP(DD / 128, NT / 128, 1);
    gemm_k<128,128,16,8,8,true,0><<<gP, 256>>>(xq, DD,0,0, Wq, DD,0,0, q, DD,0,0, DD,
        bq, nullptr,nullptr,nullptr,nullptr,nullptr, nullptr,0);
    gemm_k<128,128,16,8,8,true,0><<<gP, 256>>>(x,  DD,0,0, Wk, DD,0,0, k, DD,0,0, DD,
        bk, nullptr,nullptr,nullptr,nullptr,nullptr, nullptr,0);
    gemm_k<128,128,16,8,8,true,0><<<gP, 256>>>(x,  DD,0,0, Wv, DD,0,0, v, DD,0,0, DD,
        bv, nullptr,nullptr,nullptr,nullptr,nullptr, nullptr,0);

    // 3) scores = Q K^T / 8 (+mask), batched over (b,h), written into d_out attn region
    dim3 gS(SS / 128, SS / 128, BB * HH);
    gemm_k<128,128,16,8,8,true,3><<<gS, 256>>>(
        q, DD, (long)SS * DD, 64,
        k, DD, (long)SS * DD, 64,
        outa, SS, (long)HH * SS * SS, (long)SS * SS,
        DK, nullptr, nullptr, nullptr,nullptr,nullptr,nullptr, mask, SS);

    // 4) softmax in place (this IS the attn output)
    softmax_k<<<BB * HH * SS, 256>>>(outa);

    // 5) context = attn @ V  (NN GEMM, batched)
    dim3 gC(DK / 64, SS / 64, BB * HH);
    gemm_k<64,64,16,4,4,false,4><<<gC, 256>>>(
        outa, SS, (long)HH * SS * SS, (long)SS * SS,
        v,    DD, (long)SS * DD, 64,
        ctx,  DD, (long)SS * DD, 64,
        SS, nullptr, nullptr, nullptr,nullptr,nullptr,nullptr, nullptr,0);

    // 6) O projection + residual(x) + bn1 -> x1
    gemm_k<128,128,16,8,8,true,1><<<gP, 256>>>(ctx, DD,0,0, Wo, DD,0,0, x1, DD,0,0, DD,
        bo, x, bn1g,bn1b,bn1m,bn1v, nullptr,0);

    // 7) FFN pre-LN
    ln_k<<<NT, 256>>>(x1, lfg, lfb, xq);

    // 8) h = bnff(gelu(xn W1^T + b1))   M=8192 N=4096 K=1024
    dim3 g1(DF / 128, NT / 128, 1);
    gemm_k<128,128,16,8,8,true,2><<<g1, 256>>>(xq, DD,0,0, W1, DD,0,0, h, DF,0,0, DD,
        b1, nullptr, bnffg,bnffb,bnffm,bnffv, nullptr,0);

    // 9) out_x = bn2(h W2^T + b2 + x1)  M=8192 N=1024 K=4096
    dim3 g2(DD / 128, NT / 128, 1);
    gemm_k<128,128,16,8,8,true,1><<<g2, 256>>>(h, DF,0,0, W2, DF,0,0, outx, DD,0,0, DF,
        b2, x1, bn2g,bn2b,bn2m,bn2v, nullptr,0);
}

// round 2
// speedup vs baseline: 2.9866x; 2.9866x over previous
#include <cuda_runtime.h>
#include <math.h>

#define BB   8
#define SS   1024
#define DD   1024
#define HH   16
#define DKK  64
#define DF   4096
#define NTOK (BB*SS)        // 8192 tokens

// ---------------- scratch (static device globals; no allocation) ------------
__device__ float g_xq[NTOK*DD];
__device__ float g_q [NTOK*DD];
__device__ float g_k [NTOK*DD];
__device__ float g_v [NTOK*DD];
__device__ float g_ctx[NTOK*DD];
__device__ float g_x1[NTOK*DD];
__device__ float g_h [NTOK*DF];

// ---------------- small PTX helpers -----------------------------------------
__device__ __forceinline__ unsigned f2tf(float f) {
    unsigned u;
    asm("cvt.rna.tf32.f32 %0, %1;" : "=r"(u) : "f"(f));
    return u;
}
__device__ __forceinline__ void cpa16(float* s, const float* g) {
    unsigned sa = (unsigned)__cvta_generic_to_shared(s);
    asm volatile("cp.async.cg.shared.global [%0], [%1], 16;" :: "r"(sa), "l"(g));
}
__device__ __forceinline__ void cp_commit() {
    asm volatile("cp.async.commit_group;");
}
template<int N> __device__ __forceinline__ void cp_wait() {
    asm volatile("cp.async.wait_group %0;" :: "n"(N));
}
__device__ __forceinline__ void mma8(float* c, const unsigned* a, const unsigned* b) {
    asm volatile(
        "mma.sync.aligned.m16n8k8.row.col.f32.tf32.tf32.f32 "
        "{%0,%1,%2,%3}, {%4,%5,%6,%7}, {%8,%9}, {%0,%1,%2,%3};"
        : "+f"(c[0]), "+f"(c[1]), "+f"(c[2]), "+f"(c[3])
        : "r"(a[0]), "r"(a[1]), "r"(a[2]), "r"(a[3]), "r"(b[0]), "r"(b[1]));
}

// ---------------- tf32 tensor-core GEMM --------------------------------------
// C = A (MxK) * op(B) + epilogue.
// BT=true : B is [N,K] row-major (A*B^T).  BT=false: B is [K,N] row-major (A*B).
// Batched over blockIdx.z: offsets (z/16)*s1 + (z%16)*s2 per operand.
// MODE: 0 bias | 1 bias+res+BN | 2 bias+GELU+BN | 3 mask-scale (scores) | 4 raw
template<int BM,int BN,int WM,int WN,bool BT,int MODE>
__global__ void __launch_bounds__(256)
gemm_tc(const float* __restrict__ A, int lda, long aS1, long aS2,
        const float* __restrict__ B, int ldb, long bS1, long bS2,
        float*       __restrict__ C, int ldc, long cS1, long cS2,
        int K,
        const float* __restrict__ bias,
        const float* __restrict__ res,
        const float* __restrict__ bng, const float* __restrict__ bnb,
        const float* __restrict__ bnm, const float* __restrict__ bnv,
        const int*   __restrict__ mask, int maskS1)
{
    constexpr int BK  = 16;
    constexpr int AST = BK + 4;                      // A smem row stride (floats)
    constexpr int BST = BT ? (BK + 4) : (BN + 4);    // B smem row stride
    constexpr int ASZ = BM * AST;
    constexpr int BSZ = BT ? BN * BST : BK * BST;

    __shared__ float sA[2][ASZ];
    __shared__ float sB[2][BSZ];

    const int z  = blockIdx.z;
    const int zb = z >> 4;
    const int zh = z & 15;
    A += (long)zb * aS1 + (long)zh * aS2;
    B += (long)zb * bS1 + (long)zh * bS2;
    C += (long)zb * cS1 + (long)zh * cS2;

    const int tid = threadIdx.x;
    const int m0  = blockIdx.y * BM;
    const int n0  = blockIdx.x * BN;

    const int warp = tid >> 5, lane = tid & 31;
    constexpr int WGN = BN / WN;                 // warps along N
    const int wm = warp / WGN, wn = warp % WGN;
    const int g  = lane >> 2,  t  = lane & 3;
    constexpr int MT  = WM / 16;
    constexpr int NTL = WN / 8;

    float c[MT][NTL][4];
    #pragma unroll
    for (int i = 0; i < MT; i++)
        #pragma unroll
        for (int j = 0; j < NTL; j++)
            #pragma unroll
            for (int e = 0; e < 4; e++) c[i][j][e] = 0.0f;

    const int iters = K / BK;

    auto load_stage = [&](int it, int buf) {
        const int k0 = it * BK;
        constexpr int ASEG = BM * (BK / 4);          // 16B segments of A
        #pragma unroll
        for (int s = tid; s < ASEG; s += 256) {
            int row = s >> 2, seg = s & 3;
            cpa16(&sA[buf][row * AST + seg * 4],
                  A + (long)(m0 + row) * lda + k0 + seg * 4);
        }
        if constexpr (BT) {
            constexpr int BSEG = BN * (BK / 4);
            #pragma unroll
            for (int s = tid; s < BSEG; s += 256) {
                int row = s >> 2, seg = s & 3;
                cpa16(&sB[buf][row * BST + seg * 4],
                      B + (long)(n0 + row) * ldb + k0 + seg * 4);
            }
        } else {
            constexpr int SPR  = BN / 4;
            constexpr int BSEG = BK * SPR;
            #pragma unroll
            for (int s = tid; s < BSEG; s += 256) {
                int row = s / SPR, seg = s % SPR;
                cpa16(&sB[buf][row * BST + seg * 4],
                      B + (long)(k0 + row) * ldb + n0 + seg * 4);
            }
        }
    };

    load_stage(0, 0);
    cp_commit();

    for (int it = 0; it < iters; ++it) {
        const int buf = it & 1;
        if (it + 1 < iters) { load_stage(it + 1, buf ^ 1); cp_commit(); cp_wait<1>(); }
        else                { cp_wait<0>(); }
        __syncthreads();

        #pragma unroll
        for (int kb = 0; kb < BK; kb += 8) {
            unsigned a[MT][4], b[NTL][2];
            #pragma unroll
            for (int mt = 0; mt < MT; mt++) {
                const int mr = wm * WM + mt * 16 + g;
                a[mt][0] = f2tf(sA[buf][(mr    ) * AST + kb + t    ]);
                a[mt][1] = f2tf(sA[buf][(mr + 8) * AST + kb + t    ]);
                a[mt][2] = f2tf(sA[buf][(mr    ) * AST + kb + t + 4]);
                a[mt][3] = f2tf(sA[buf][(mr + 8) * AST + kb + t + 4]);
            }
            #pragma unroll
            for (int nt = 0; nt < NTL; nt++) {
                const int nc = wn * WN + nt * 8 + g;
                if constexpr (BT) {
                    b[nt][0] = f2tf(sB[buf][nc * BST + kb + t    ]);
                    b[nt][1] = f2tf(sB[buf][nc * BST + kb + t + 4]);
                } else {
                    b[nt][0] = f2tf(sB[buf][(kb + t    ) * BST + nc]);
                    b[nt][1] = f2tf(sB[buf][(kb + t + 4) * BST + nc]);
                }
            }
            #pragma unroll
            for (int mt = 0; mt < MT; mt++)
                #pragma unroll
                for (int nt = 0; nt < NTL; nt++)
                    mma8(c[mt][nt], a[mt], b[nt]);
        }
        __syncthreads();
    }

    // ---- epilogue ----
    auto ep = [&](float v, int n, long m) -> float {
        if constexpr (MODE == 0) {
            v += bias[n];
        } else if constexpr (MODE == 1) {
            v += bias[n] + res[m * ldc + n];
            v = (v - bnm[n]) * rsqrtf(bnv[n] + 1e-5f) * bng[n] + bnb[n];
        } else if constexpr (MODE == 2) {
            v += bias[n];
            v = 0.5f * v * (1.0f + erff(v * 0.70710678118654752f));
            v = (v - bnm[n]) * rsqrtf(bnv[n] + 1e-5f) * bng[n] + bnb[n];
        } else if constexpr (MODE == 3) {
            v = (mask[(long)zb * maskS1 + n] == 0) ? -1e9f : v * 0.125f;
        }
        return v;
    };

    #pragma unroll
    for (int mt = 0; mt < MT; mt++) {
        #pragma unroll
        for (int nt = 0; nt < NTL; nt++) {
            const int row = m0 + wm * WM + mt * 16 + g;
            const int col = n0 + wn * WN + nt * 8 + 2 * t;
            float2 r0, r1;
            r0.x = ep(c[mt][nt][0], col,     row);
            r0.y = ep(c[mt][nt][1], col + 1, row);
            r1.x = ep(c[mt][nt][2], col,     row + 8);
            r1.y = ep(c[mt][nt][3], col + 1, row + 8);
            *(float2*)&C[(long)(row    ) * ldc + col] = r0;
            *(float2*)&C[(long)(row + 8) * ldc + col] = r1;
        }
    }
}

// ---------------- LayerNorm over last dim (D=1024), 1 block/row -------------
__global__ void __launch_bounds__(256)
ln_k(const float* __restrict__ x, const float* __restrict__ g,
     const float* __restrict__ b, float* __restrict__ o)
{
    __shared__ float red[8];
    const long row = blockIdx.x;
    const int  t = threadIdx.x, lane = t & 31, w = t >> 5;

    float4 v = ((const float4*)(x + row * DD))[t];
    float s = v.x + v.y + v.z + v.w;
    #pragma unroll
    for (int off = 16; off; off >>= 1) s += __shfl_down_sync(0xffffffffu, s, off);
    if (!lane) red[w] = s;
    __syncthreads();
    if (t == 0) { float a = 0.f; for (int i = 0; i < 8; i++) a += red[i]; red[0] = a; }
    __syncthreads();
    const float mu = red[0] * (1.0f / DD);
    __syncthreads();

    float d0 = v.x - mu, d1 = v.y - mu, d2 = v.z - mu, d3 = v.w - mu;
    float sq = d0*d0 + d1*d1 + d2*d2 + d3*d3;
    #pragma unroll
    for (int off = 16; off; off >>= 1) sq += __shfl_down_sync(0xffffffffu, sq, off);
    if (!lane) red[w] = sq;
    __syncthreads();
    if (t == 0) { float a = 0.f; for (int i = 0; i < 8; i++) a += red[i]; red[0] = a; }
    __syncthreads();
    const float rs = rsqrtf(red[0] * (1.0f / DD) + 1e-5f);

    float4 g4 = ((const float4*)g)[t];
    float4 b4 = ((const float4*)b)[t];
    float4 r;
    r.x = d0 * rs * g4.x + b4.x;
    r.y = d1 * rs * g4.y + b4.y;
    r.z = d2 * rs * g4.z + b4.z;
    r.w = d3 * rs * g4.w + b4.w;
    ((float4*)(o + row * DD))[t] = r;
}

// ---------------- row softmax over S=1024, 1 block/row, in-place ------------
__global__ void __launch_bounds__(256)
softmax_k(float* __restrict__ a)
{
    __shared__ float red[8];
    const long row = blockIdx.x;
    const int  t = threadIdx.x, lane = t & 31, w = t >> 5;

    float4* p = (float4*)(a + row * (long)SS);
    float4 v = p[t];
    float mx = fmaxf(fmaxf(v.x, v.y), fmaxf(v.z, v.w));
    #pragma unroll
    for (int off = 16; off; off >>= 1)
        mx = fmaxf(mx, __shfl_down_sync(0xffffffffu, mx, off));
    if (!lane) red[w] = mx;
    __syncthreads();
    if (t == 0) { float m = red[0]; for (int i = 1; i < 8; i++) m = fmaxf(m, red[i]); red[0] = m; }
    __syncthreads();
    const float rmax = red[0];
    __syncthreads();

    float e0 = __expf(v.x - rmax), e1 = __expf(v.y - rmax);
    float e2 = __expf(v.z - rmax), e3 = __expf(v.w - rmax);
    float s = e0 + e1 + e2 + e3;
    #pragma unroll
    for (int off = 16; off; off >>= 1) s += __shfl_down_sync(0xffffffffu, s, off);
    if (!lane) red[w] = s;
    __syncthreads();
    if (t == 0) { float a2 = 0.f; for (int i = 0; i < 8; i++) a2 += red[i]; red[0] = a2; }
    __syncthreads();
    const float inv = 1.0f / red[0];

    p[t] = make_float4(e0 * inv, e1 * inv, e2 * inv, e3 * inv);
}

// ---------------- host orchestration ----------------------------------------
extern "C" void kernel_launch(void* const* d_in, const int* in_sizes, int n_in,
                              void* d_out, int out_size)
{
    const float* x    = (const float*)d_in[0];
    const int*   mask = (const int*)  d_in[1];
    const float* Wq = (const float*)d_in[2];  const float* bq = (const float*)d_in[3];
    const float* Wk = (const float*)d_in[4];  const float* bk = (const float*)d_in[5];
    const float* Wv = (const float*)d_in[6];  const float* bv = (const float*)d_in[7];
    const float* Wo = (const float*)d_in[8];  const float* bo = (const float*)d_in[9];
    const float* lag = (const float*)d_in[10]; const float* lab = (const float*)d_in[11];
    const float* W1 = (const float*)d_in[12]; const float* b1 = (const float*)d_in[13];
    const float* W2 = (const float*)d_in[14]; const float* b2 = (const float*)d_in[15];
    const float* lfg = (const float*)d_in[16]; const float* lfb = (const float*)d_in[17];
    const float* bnffg = (const float*)d_in[18]; const float* bnffb = (const float*)d_in[19];
    const float* bnffm = (const float*)d_in[20]; const float* bnffv = (const float*)d_in[21];
    const float* bn1g = (const float*)d_in[22]; const float* bn1b = (const float*)d_in[23];
    const float* bn1m = (const float*)d_in[24]; const float* bn1v = (const float*)d_in[25];
    const float* bn2g = (const float*)d_in[26]; const float* bn2b = (const float*)d_in[27];
    const float* bn2m = (const float*)d_in[28]; const float* bn2v = (const float*)d_in[29];

    float *xq, *q, *k, *v, *ctx, *x1, *h;
    cudaGetSymbolAddress((void**)&xq,  g_xq);
    cudaGetSymbolAddress((void**)&q,   g_q);
    cudaGetSymbolAddress((void**)&k,   g_k);
    cudaGetSymbolAddress((void**)&v,   g_v);
    cudaGetSymbolAddress((void**)&ctx, g_ctx);
    cudaGetSymbolAddress((void**)&x1,  g_x1);
    cudaGetSymbolAddress((void**)&h,   g_h);

    float* outx = (float*)d_out;                    // [B,S,D]
    float* outa = outx + (long)NTOK * DD;           // [B,H,S,S]

    // 1) pre-LN for query path
    ln_k<<<NTOK, 256>>>(x, lag, lab, xq);

    // 2) Q,K,V projections (M=8192 N=1024 K=1024)
    dim3 gP(DD / 128, NTOK / 128, 1);
    gemm_tc<128,128,64,32,true,0><<<gP, 256>>>(xq, DD,0,0, Wq, DD,0,0, q, DD,0,0, DD,
        bq, nullptr, nullptr,nullptr,nullptr,nullptr, nullptr,0);
    gemm_tc<128,128,64,32,true,0><<<gP, 256>>>(x,  DD,0,0, Wk, DD,0,0, k, DD,0,0, DD,
        bk, nullptr, nullptr,nullptr,nullptr,nullptr, nullptr,0);
    gemm_tc<128,128,64,32,true,0><<<gP, 256>>>(x,  DD,0,0, Wv, DD,0,0, v, DD,0,0, DD,
        bv, nullptr, nullptr,nullptr,nullptr,nullptr, nullptr,0);

    // 3) scores = Q K^T / 8 (+mask), batched over (b,h), into d_out attn region
    dim3 gS(SS / 128, SS / 128, BB * HH);
    gemm_tc<128,128,64,32,true,3><<<gS, 256>>>(
        q, DD, (long)SS * DD, 64,
        k, DD, (long)SS * DD, 64,
        outa, SS, (long)HH * SS * SS, (long)SS * SS,
        DKK, nullptr, nullptr, nullptr,nullptr,nullptr,nullptr, mask, SS);

    // 4) softmax in place (this IS the attn output)
    softmax_k<<<BB * HH * SS, 256>>>(outa);

    // 5) context = attn @ V  (NN GEMM, batched, N=64)
    dim3 gC(1, SS / 128, BB * HH);
    gemm_tc<128,64,32,32,false,4><<<gC, 256>>>(
        outa, SS, (long)HH * SS * SS, (long)SS * SS,
        v,    DD, (long)SS * DD, 64,
        ctx,  DD, (long)SS * DD, 64,
        SS, nullptr, nullptr, nullptr,nullptr,nullptr,nullptr, nullptr,0);

    // 6) O projection + residual(x) + bn1 -> x1
    gemm_tc<128,128,64,32,true,1><<<gP, 256>>>(ctx, DD,0,0, Wo, DD,0,0, x1, DD,0,0, DD,
        bo, x, bn1g,bn1b,bn1m,bn1v, nullptr,0);

    // 7) FFN pre-LN
    ln_k<<<NTOK, 256>>>(x1, lfg, lfb, xq);

    // 8) h = bnff(gelu(xn W1^T + b1))   M=8192 N=4096 K=1024
    dim3 g1(DF / 128, NTOK / 128, 1);
    gemm_tc<128,128,64,32,true,2><<<g1, 256>>>(xq, DD,0,0, W1, DD,0,0, h, DF,0,0, DD,
        b1, nullptr, bnffg,bnffb,bnffm,bnffv, nullptr,0);

    // 9) out_x = bn2(h W2^T + b2 + x1)  M=8192 N=1024 K=4096
    dim3 g2(DD / 128, NTOK / 128, 1);
    gemm_tc<128,128,64,32,true,1><<<g2, 256>>>(h, DF,0,0, W2, DF,0,0, outx, DD,0,0, DF,
        b2, x1, bn2g,bn2b,bn2m,bn2v, nullptr,0);
}

// round 4
// speedup vs baseline: 3.0908x; 1.0349x over previous
#include <cuda_runtime.h>
#include <math.h>

#define BB   8
#define SS   1024
#define DD   1024
#define HH   16
#define DKK  64
#define DF   4096
#define NTOK (BB*SS)        // 8192 tokens

// ---------------- scratch (static device globals; no allocation) ------------
__device__ float g_xq[NTOK*DD];        // LN output (rounded), reused for both LNs
__device__ float g_xr[NTOK*DD];        // x rounded to tf32
__device__ float g_q [NTOK*DD];
__device__ float g_k [NTOK*DD];
__device__ float g_v [NTOK*DD];
__device__ float g_ctx[NTOK*DD];
__device__ float g_x1[NTOK*DD];        // after bn1 (exact fp32; residual source)
__device__ float g_h [NTOK*DF];        // FFN hidden (rounded)
__device__ float g_w [12*1024*1024];   // rounded weights: Wq Wk Wv Wo | W1 | W2

// ---------------- small PTX helpers -----------------------------------------
__device__ __forceinline__ unsigned f2tf(float f) {
    unsigned u;
    asm("cvt.rna.tf32.f32 %0, %1;" : "=r"(u) : "f"(f));
    return u;
}
__device__ __forceinline__ float roundtf(float f) {
    return __uint_as_float(f2tf(f));
}
__device__ __forceinline__ void cpa16(float* s, const float* g) {
    unsigned sa = (unsigned)__cvta_generic_to_shared(s);
    asm volatile("cp.async.cg.shared.global [%0], [%1], 16;" :: "r"(sa), "l"(g));
}
__device__ __forceinline__ void cp_commit() {
    asm volatile("cp.async.commit_group;");
}
template<int N> __device__ __forceinline__ void cp_wait() {
    asm volatile("cp.async.wait_group %0;" :: "n"(N));
}
__device__ __forceinline__ void mma8(float* c, const unsigned* a, const unsigned* b) {
    asm volatile(
        "mma.sync.aligned.m16n8k8.row.col.f32.tf32.tf32.f32 "
        "{%0,%1,%2,%3}, {%4,%5,%6,%7}, {%8,%9}, {%0,%1,%2,%3};"
        : "+f"(c[0]), "+f"(c[1]), "+f"(c[2]), "+f"(c[3])
        : "r"(a[0]), "r"(a[1]), "r"(a[2]), "r"(a[3]), "r"(b[0]), "r"(b[1]));
}

// ---------------- elementwise tf32 rounding (float4) ------------------------
__global__ void __launch_bounds__(256)
round_k(const float* __restrict__ in, float* __restrict__ out, int n4)
{
    int i = blockIdx.x * 256 + threadIdx.x;
    if (i < n4) {
        float4 v = ((const float4*)in)[i];
        v.x = roundtf(v.x); v.y = roundtf(v.y);
        v.z = roundtf(v.z); v.w = roundtf(v.w);
        ((float4*)out)[i] = v;
    }
}

// ---------------- tf32 tensor-core GEMM (3-stage cp.async) ------------------
// C = A (MxK) * op(B) + epilogue. 3-stage pipeline, dynamic smem.
// BT=true : B is [N,K] row-major (A*B^T). BT=false: B is [K,N] row-major.
// CVTA/CVTB: convert fragment to tf32 in-loop (only needed for exact-fp32 A/B).
// RND: round stored result to tf32 (for intermediates feeding later GEMMs).
// MODE: 0 bias | 1 bias+res+BN | 2 bias+GELU+BN | 3 mask-scale | 4 raw
template<int BM,int BN,int WM,int WN,bool BT,int MODE,bool CVTA,bool CVTB,bool RND>
__global__ void __launch_bounds__(256)
gemm_tc(const float* __restrict__ A, int lda, long aS1, long aS2,
        const float* __restrict__ B, int ldb, long bS1, long bS2,
        float*       __restrict__ C, int ldc, long cS1, long cS2,
        int K,
        const float* __restrict__ bias,
        const float* __restrict__ res,
        const float* __restrict__ bng, const float* __restrict__ bnb,
        const float* __restrict__ bnm, const float* __restrict__ bnv,
        const int*   __restrict__ mask, int maskS1)
{
    constexpr int BK  = 16;
    constexpr int ST  = 3;                           // pipeline stages
    constexpr int AST = BK + 4;
    constexpr int BST = BT ? (BK + 4) : (BN + 4);
    constexpr int ASZ = BM * AST;
    constexpr int BSZ = BT ? BN * BST : BK * BST;

    extern __shared__ float smem[];
    float* sA = smem;                  // [ST][ASZ]
    float* sB = smem + ST * ASZ;       // [ST][BSZ]

    const int z  = blockIdx.z;
    const int zb = z >> 4;
    const int zh = z & 15;
    A += (long)zb * aS1 + (long)zh * aS2;
    B += (long)zb * bS1 + (long)zh * bS2;
    C += (long)zb * cS1 + (long)zh * cS2;

    const int tid = threadIdx.x;
    const int m0  = blockIdx.y * BM;
    const int n0  = blockIdx.x * BN;

    const int warp = tid >> 5, lane = tid & 31;
    constexpr int WGN = BN / WN;
    const int wm = warp / WGN, wn = warp % WGN;
    const int g  = lane >> 2,  t  = lane & 3;
    constexpr int MT  = WM / 16;
    constexpr int NTL = WN / 8;

    float c[MT][NTL][4];
    #pragma unroll
    for (int i = 0; i < MT; i++)
        #pragma unroll
        for (int j = 0; j < NTL; j++)
            #pragma unroll
            for (int e = 0; e < 4; e++) c[i][j][e] = 0.0f;

    const int iters = K / BK;

    auto load_stage = [&](int it, int buf) {
        const int k0 = it * BK;
        float* dA = sA + buf * ASZ;
        float* dB = sB + buf * BSZ;
        constexpr int ASEG = BM * (BK / 4);
        #pragma unroll
        for (int s = tid; s < ASEG; s += 256) {
            int row = s >> 2, seg = s & 3;
            cpa16(&dA[row * AST + seg * 4],
                  A + (long)(m0 + row) * lda + k0 + seg * 4);
        }
        if constexpr (BT) {
            constexpr int BSEG = BN * (BK / 4);
            #pragma unroll
            for (int s = tid; s < BSEG; s += 256) {
                int row = s >> 2, seg = s & 3;
                cpa16(&dB[row * BST + seg * 4],
                      B + (long)(n0 + row) * ldb + k0 + seg * 4);
            }
        } else {
            constexpr int SPR  = BN / 4;
            constexpr int BSEG = BK * SPR;
            #pragma unroll
            for (int s = tid; s < BSEG; s += 256) {
                int row = s / SPR, seg = s % SPR;
                cpa16(&dB[row * BST + seg * 4],
                      B + (long)(k0 + row) * ldb + n0 + seg * 4);
            }
        }
    };

    // prologue: commit exactly ST-1 groups
    load_stage(0, 0);
    cp_commit();
    if (iters > 1) load_stage(1, 1);
    cp_commit();

    for (int it = 0; it < iters; ++it) {
        cp_wait<ST - 2>();
        __syncthreads();

        if (it + ST - 1 < iters) load_stage(it + ST - 1, (it + ST - 1) % ST);
        cp_commit();

        const int buf = it % ST;
        const float* bA = sA + buf * ASZ;
        const float* bB = sB + buf * BSZ;

        #pragma unroll
        for (int kb = 0; kb < BK; kb += 8) {
            unsigned a[MT][4], b[NTL][2];
            #pragma unroll
            for (int mt = 0; mt < MT; mt++) {
                const int mr = wm * WM + mt * 16 + g;
                float f0 = bA[(mr    ) * AST + kb + t    ];
                float f1 = bA[(mr + 8) * AST + kb + t    ];
                float f2 = bA[(mr    ) * AST + kb + t + 4];
                float f3 = bA[(mr + 8) * AST + kb + t + 4];
                if constexpr (CVTA) {
                    a[mt][0] = f2tf(f0); a[mt][1] = f2tf(f1);
                    a[mt][2] = f2tf(f2); a[mt][3] = f2tf(f3);
                } else {
                    a[mt][0] = __float_as_uint(f0); a[mt][1] = __float_as_uint(f1);
                    a[mt][2] = __float_as_uint(f2); a[mt][3] = __float_as_uint(f3);
                }
            }
            #pragma unroll
            for (int nt = 0; nt < NTL; nt++) {
                const int nc = wn * WN + nt * 8 + g;
                float f0, f1;
                if constexpr (BT) {
                    f0 = bB[nc * BST + kb + t    ];
                    f1 = bB[nc * BST + kb + t + 4];
                } else {
                    f0 = bB[(kb + t    ) * BST + nc];
                    f1 = bB[(kb + t + 4) * BST + nc];
                }
                if constexpr (CVTB) { b[nt][0] = f2tf(f0); b[nt][1] = f2tf(f1); }
                else { b[nt][0] = __float_as_uint(f0); b[nt][1] = __float_as_uint(f1); }
            }
            #pragma unroll
            for (int mt = 0; mt < MT; mt++)
                #pragma unroll
                for (int nt = 0; nt < NTL; nt++)
                    mma8(c[mt][nt], a[mt], b[nt]);
        }
    }

    // ---- epilogue ----
    auto ep = [&](float v, int n, long m) -> float {
        if constexpr (MODE == 0) {
            v += bias[n];
        } else if constexpr (MODE == 1) {
            v += bias[n] + res[m * ldc + n];
            v = (v - bnm[n]) * rsqrtf(bnv[n] + 1e-5f) * bng[n] + bnb[n];
        } else if constexpr (MODE == 2) {
            v += bias[n];
            v = 0.5f * v * (1.0f + erff(v * 0.70710678118654752f));
            v = (v - bnm[n]) * rsqrtf(bnv[n] + 1e-5f) * bng[n] + bnb[n];
        } else if constexpr (MODE == 3) {
            v = (mask[(long)zb * maskS1 + n] == 0) ? -1e9f : v * 0.125f;
        }
        if constexpr (RND) v = roundtf(v);
        return v;
    };

    #pragma unroll
    for (int mt = 0; mt < MT; mt++) {
        #pragma unroll
        for (int nt = 0; nt < NTL; nt++) {
            const int row = m0 + wm * WM + mt * 16 + g;
            const int col = n0 + wn * WN + nt * 8 + 2 * t;
            float2 r0, r1;
            r0.x = ep(c[mt][nt][0], col,     row);
            r0.y = ep(c[mt][nt][1], col + 1, row);
            r1.x = ep(c[mt][nt][2], col,     row + 8);
            r1.y = ep(c[mt][nt][3], col + 1, row + 8);
            *(float2*)&C[(long)(row    ) * ldc + col] = r0;
            *(float2*)&C[(long)(row + 8) * ldc + col] = r1;
        }
    }
}

// ---------------- LayerNorm over last dim (D=1024); output tf32-rounded -----
__global__ void __launch_bounds__(256)
ln_k(const float* __restrict__ x, const float* __restrict__ g,
     const float* __restrict__ b, float* __restrict__ o)
{
    __shared__ float red[8];
    const long row = blockIdx.x;
    const int  t = threadIdx.x, lane = t & 31, w = t >> 5;

    float4 v = ((const float4*)(x + row * DD))[t];
    float s = v.x + v.y + v.z + v.w;
    #pragma unroll
    for (int off = 16; off; off >>= 1) s += __shfl_down_sync(0xffffffffu, s, off);
    if (!lane) red[w] = s;
    __syncthreads();
    if (t == 0) { float a = 0.f; for (int i = 0; i < 8; i++) a += red[i]; red[0] = a; }
    __syncthreads();
    const float mu = red[0] * (1.0f / DD);
    __syncthreads();

    float d0 = v.x - mu, d1 = v.y - mu, d2 = v.z - mu, d3 = v.w - mu;
    float sq = d0*d0 + d1*d1 + d2*d2 + d3*d3;
    #pragma unroll
    for (int off = 16; off; off >>= 1) sq += __shfl_down_sync(0xffffffffu, sq, off);
    if (!lane) red[w] = sq;
    __syncthreads();
    if (t == 0) { float a = 0.f; for (int i = 0; i < 8; i++) a += red[i]; red[0] = a; }
    __syncthreads();
    const float rs = rsqrtf(red[0] * (1.0f / DD) + 1e-5f);

    float4 g4 = ((const float4*)g)[t];
    float4 b4 = ((const float4*)b)[t];
    float4 r;
    r.x = roundtf(d0 * rs * g4.x + b4.x);
    r.y = roundtf(d1 * rs * g4.y + b4.y);
    r.z = roundtf(d2 * rs * g4.z + b4.z);
    r.w = roundtf(d3 * rs * g4.w + b4.w);
    ((float4*)(o + row * DD))[t] = r;
}

// ---------------- row softmax over S=1024, in-place (exact fp32) ------------
__global__ void __launch_bounds__(256)
softmax_k(float* __restrict__ a)
{
    __shared__ float red[8];
    const long row = blockIdx.x;
    const int  t = threadIdx.x, lane = t & 31, w = t >> 5;

    float4* p = (float4*)(a + row * (long)SS);
    float4 v = p[t];
    float mx = fmaxf(fmaxf(v.x, v.y), fmaxf(v.z, v.w));
    #pragma unroll
    for (int off = 16; off; off >>= 1)
        mx = fmaxf(mx, __shfl_down_sync(0xffffffffu, mx, off));
    if (!lane) red[w] = mx;
    __syncthreads();
    if (t == 0) { float m = red[0]; for (int i = 1; i < 8; i++) m = fmaxf(m, red[i]); red[0] = m; }
    __syncthreads();
    const float rmax = red[0];
    __syncthreads();

    float e0 = __expf(v.x - rmax), e1 = __expf(v.y - rmax);
    float e2 = __expf(v.z - rmax), e3 = __expf(v.w - rmax);
    float s = e0 + e1 + e2 + e3;
    #pragma unroll
    for (int off = 16; off; off >>= 1) s += __shfl_down_sync(0xffffffffu, s, off);
    if (!lane) red[w] = s;
    __syncthreads();
    if (t == 0) { float a2 = 0.f; for (int i = 0; i < 8; i++) a2 += red[i]; red[0] = a2; }
    __syncthreads();
    const float inv = 1.0f / red[0];

    p[t] = make_float4(e0 * inv, e1 * inv, e2 * inv, e3 * inv);
}

// ---------------- host orchestration ----------------------------------------
extern "C" void kernel_launch(void* const* d_in, const int* in_sizes, int n_in,
                              void* d_out, int out_size)
{
    const float* x    = (const float*)d_in[0];
    const int*   mask = (const int*)  d_in[1];
    const float* Wq = (const float*)d_in[2];  const float* bq = (const float*)d_in[3];
    const float* Wk = (const float*)d_in[4];  const float* bk = (const float*)d_in[5];
    const float* Wv = (const float*)d_in[6];  const float* bv = (const float*)d_in[7];
    const float* Wo = (const float*)d_in[8];  const float* bo = (const float*)d_in[9];
    const float* lag = (const float*)d_in[10]; const float* lab = (const float*)d_in[11];
    const float* W1 = (const float*)d_in[12]; const float* b1 = (const float*)d_in[13];
    const float* W2 = (const float*)d_in[14]; const float* b2 = (const float*)d_in[15];
    const float* lfg = (const float*)d_in[16]; const float* lfb = (const float*)d_in[17];
    const float* bnffg = (const float*)d_in[18]; const float* bnffb = (const float*)d_in[19];
    const float* bnffm = (const float*)d_in[20]; const float* bnffv = (const float*)d_in[21];
    const float* bn1g = (const float*)d_in[22]; const float* bn1b = (const float*)d_in[23];
    const float* bn1m = (const float*)d_in[24]; const float* bn1v = (const float*)d_in[25];
    const float* bn2g = (const float*)d_in[26]; const float* bn2b = (const float*)d_in[27];
    const float* bn2m = (const float*)d_in[28]; const float* bn2v = (const float*)d_in[29];

    float *xq, *xr, *q, *k, *v, *ctx, *x1, *h, *w;
    cudaGetSymbolAddress((void**)&xq,  g_xq);
    cudaGetSymbolAddress((void**)&xr,  g_xr);
    cudaGetSymbolAddress((void**)&q,   g_q);
    cudaGetSymbolAddress((void**)&k,   g_k);
    cudaGetSymbolAddress((void**)&v,   g_v);
    cudaGetSymbolAddress((void**)&ctx, g_ctx);
    cudaGetSymbolAddress((void**)&x1,  g_x1);
    cudaGetSymbolAddress((void**)&h,   g_h);
    cudaGetSymbolAddress((void**)&w,   g_w);

    float* cWq = w;                    // 1M floats each
    float* cWk = w + 1*1024*1024;
    float* cWv = w + 2*1024*1024;
    float* cWo = w + 3*1024*1024;
    float* cW1 = w + 4*1024*1024;      // 4M
    float* cW2 = w + 8*1024*1024;      // 4M

    float* outx = (float*)d_out;                    // [B,S,D]
    float* outa = outx + (long)NTOK * DD;           // [B,H,S,S]

    // ---- opt into >48KB dynamic smem for the big instantiations ----
    constexpr int SM_BIG = 3 * (128*20 + 128*20) * 4;   // 61440 B
    constexpr int SM_AV  = 3 * (128*20 + 16*68) * 4;    // 43776 B
    auto* kP = gemm_tc<128,128,64,32,true ,0,false,false,true >;
    auto* kS = gemm_tc<128,128,64,32,true ,3,false,false,false>;
    auto* kAV= gemm_tc<128, 64,32,32,false,4,true ,false,true >;
    auto* kR = gemm_tc<128,128,64,32,true ,1,false,false,false>;
    auto* kG = gemm_tc<128,128,64,32,true ,2,false,false,true >;
    cudaFuncSetAttribute((const void*)kP,  cudaFuncAttributeMaxDynamicSharedMemorySize, SM_BIG);
    cudaFuncSetAttribute((const void*)kS,  cudaFuncAttributeMaxDynamicSharedMemorySize, SM_BIG);
    cudaFuncSetAttribute((const void*)kAV, cudaFuncAttributeMaxDynamicSharedMemorySize, SM_AV);
    cudaFuncSetAttribute((const void*)kR,  cudaFuncAttributeMaxDynamicSharedMemorySize, SM_BIG);
    cudaFuncSetAttribute((const void*)kG,  cudaFuncAttributeMaxDynamicSharedMemorySize, SM_BIG);

    // 0) pre-round weights + x to tf32 bit patterns
    round_k<<<(1024*1024/4 + 255)/256, 256>>>(Wq, cWq, 1024*1024/4);
    round_k<<<(1024*1024/4 + 255)/256, 256>>>(Wk, cWk, 1024*1024/4);
    round_k<<<(1024*1024/4 + 255)/256, 256>>>(Wv, cWv, 1024*1024/4);
    round_k<<<(1024*1024/4 + 255)/256, 256>>>(Wo, cWo, 1024*1024/4);
    round_k<<<(4*1024*1024/4 + 255)/256, 256>>>(W1, cW1, 4*1024*1024/4);
    round_k<<<(4*1024*1024/4 + 255)/256, 256>>>(W2, cW2, 4*1024*1024/4);
    round_k<<<(NTOK*DD/4 + 255)/256, 256>>>(x, xr, NTOK*DD/4);

    // 1) pre-LN for query path (rounded output)
    ln_k<<<NTOK, 256>>>(x, lag, lab, xq);

    // 2) Q,K,V projections (M=8192 N=1024 K=1024); outputs rounded
    dim3 gP(DD / 128, NTOK / 128, 1);
    kP<<<gP, 256, SM_BIG>>>(xq, DD,0,0, cWq, DD,0,0, q, DD,0,0, DD,
        bq, nullptr, nullptr,nullptr,nullptr,nullptr, nullptr,0);
    kP<<<gP, 256, SM_BIG>>>(xr, DD,0,0, cWk, DD,0,0, k, DD,0,0, DD,
        bk, nullptr, nullptr,nullptr,nullptr,nullptr, nullptr,0);
    kP<<<gP, 256, SM_BIG>>>(xr, DD,0,0, cWv, DD,0,0, v, DD,0,0, DD,
        bv, nullptr, nullptr,nullptr,nullptr,nullptr, nullptr,0);

    // 3) scores = Q K^T / 8 (+mask), batched over (b,h), into d_out attn region
    dim3 gS(SS / 128, SS / 128, BB * HH);
    kS<<<gS, 256, SM_BIG>>>(
        q, DD, (long)SS * DD, 64,
        k, DD, (long)SS * DD, 64,
        outa, SS, (long)HH * SS * SS, (long)SS * SS,
        DKK, nullptr, nullptr, nullptr,nullptr,nullptr,nullptr, mask, SS);

    // 4) softmax in place (this IS the attn output; exact fp32)
    softmax_k<<<BB * HH * SS, 256>>>(outa);

    // 5) context = attn @ V (attn converted in-loop; v pre-rounded)
    dim3 gC(1, SS / 128, BB * HH);
    kAV<<<gC, 256, SM_AV>>>(
        outa, SS, (long)HH * SS * SS, (long)SS * SS,
        v,    DD, (long)SS * DD, 64,
        ctx,  DD, (long)SS * DD, 64,
        SS, nullptr, nullptr, nullptr,nullptr,nullptr,nullptr, nullptr,0);

    // 6) O projection + residual(x) + bn1 -> x1 (exact fp32)
    kR<<<gP, 256, SM_BIG>>>(ctx, DD,0,0, cWo, DD,0,0, x1, DD,0,0, DD,
        bo, x, bn1g,bn1b,bn1m,bn1v, nullptr,0);

    // 7) FFN pre-LN (rounded output)
    ln_k<<<NTOK, 256>>>(x1, lfg, lfb, xq);

    // 8) h = bnff(gelu(xn W1^T + b1)), rounded  M=8192 N=4096 K=1024
    dim3 g1(DF / 128, NTOK / 128, 1);
    kG<<<g1, 256, SM_BIG>>>(xq, DD,0,0, cW1, DD,0,0, h, DF,0,0, DD,
        b1, nullptr, bnffg,bnffb,bnffm,bnffv, nullptr,0);

    // 9) out_x = bn2(h W2^T + b2 + x1)  M=8192 N=1024 K=4096
    dim3 g2(DD / 128, NTOK / 128, 1);
    kR<<<g2, 256, SM_BIG>>>(h, DF,0,0, cW2, DF,0,0, outx, DD,0,0, DF,
        b2, x1, bn2g,bn2b,bn2m,bn2v, nullptr,0);
}